// round 7
// baseline (speedup 1.0000x reference)
#include <cuda_runtime.h>

// QuantumLayer fused single-kernel, register-dieted to avoid spills:
//  z_w(x) = sum_{u,v} C[w][u][v]*p01[u]*p23[v], features (1, cos x, sin x).
// Per block: shuffle-parallel C builder (~1us) -> shared, then grid-stride
// packed-f32x2 evaluation. p23 packed (18 regs); p01 factors kept as 4 scalars
// and combined at point of use; single live float4. Demand ~60 < 80-reg cap.

#define TPB    256
#define NBLK   444                 // 3 blocks/SM * 148 SMs, all resident at t=0
#define STRIDE (NBLK * TPB)

typedef unsigned long long ull;

__device__ __forceinline__ ull pk2(float lo, float hi) {
    ull r; asm("mov.b64 %0,{%1,%2};" : "=l"(r) : "f"(lo), "f"(hi)); return r;
}
__device__ __forceinline__ void upk2(ull a, float& lo, float& hi) {
    asm("mov.b64 {%0,%1},%2;" : "=f"(lo), "=f"(hi) : "l"(a));
}
__device__ __forceinline__ ull fma2(ull a, ull b, ull c) {
    ull d; asm("fma.rn.f32x2 %0,%1,%2,%3;" : "=l"(d) : "l"(a), "l"(b), "l"(c)); return d;
}
__device__ __forceinline__ ull mul2(ull a, ull b) {
    ull d; asm("mul.rn.f32x2 %0,%1,%2;" : "=l"(d) : "l"(a), "l"(b)); return d;
}

__global__ __launch_bounds__(TPB, 3)
void qlayer_fused_kernel(const float4* __restrict__ x, float4* __restrict__ out,
                         int B, const float* __restrict__ weights) {
    __shared__ float sUr[16][16], sUi[16][16];
    __shared__ float sM[256 * 4];                 // [(j*16+k)*4 + w]
    __shared__ __align__(16) ull shC[162];        // [uv][{w01, w23}]

    const int tid = threadIdx.x;

    // ---- first chunk's global load issued before builder (latency hides) ----
    int idx = blockIdx.x * TPB + tid;
    float4 xv = make_float4(0.f, 0.f, 0.f, 0.f);
    if (idx < B) xv = x[idx];

    // ================= builder: weights -> C (per block) =================
    {
        const int i = tid & 15;                   // row (state index)
        float vr = (i == (tid >> 4)) ? 1.0f : 0.0f;
        float vi = 0.0f;
#pragma unroll
        for (int l = 0; l < 5; ++l) {
#pragma unroll
            for (int w = 0; w < 4; ++w) {
                const float phi   = __ldg(&weights[(l * 4 + w) * 3 + 0]);
                const float theta = __ldg(&weights[(l * 4 + w) * 3 + 1]);
                const float omega = __ldg(&weights[(l * 4 + w) * 3 + 2]);
                float sp, cp, sm, cm, st, ct;
                __sincosf(0.5f * (phi + omega), &sp, &cp);
                __sincosf(0.5f * (phi - omega), &sm, &cm);
                __sincosf(0.5f * theta, &st, &ct);
                const int m = 8 >> w;
                const float pr = __shfl_xor_sync(0xffffffffu, vr, m);
                const float pi = __shfl_xor_sync(0xffffffffu, vi, m);
                const bool bit = (i & m) != 0;
                const float cAr = cp * ct;
                const float cAi = bit ? sp * ct : -sp * ct;
                const float cBr = bit ? cm * st : -cm * st;
                const float cBi = -sm * st;
                const float nvr = cAr * vr - cAi * vi + cBr * pr - cBi * pi;
                const float nvi = cAr * vi + cAi * vr + cBr * pi + cBi * pr;
                vr = nvr; vi = nvi;
            }
            const int r = (l % 3) + 1;
#pragma unroll
            for (int w = 0; w < 4; ++w) {
                const int mc = 8 >> w;
                const int mt = 8 >> ((w + r) & 3);
                const float pr = __shfl_xor_sync(0xffffffffu, vr, mt);
                const float pi = __shfl_xor_sync(0xffffffffu, vi, mt);
                if (i & mc) { vr = pr; vi = pi; }
            }
        }
        sUr[i][tid >> 4] = vr;
        sUi[i][tid >> 4] = vi;
    }
    __syncthreads();

    {   // M_w[j][k] = sum_i sign_w(i) Re(conj U_ij * U_ik)
        const int j = tid >> 4, k = tid & 15;
        float m0 = 0.f, m1 = 0.f, m2 = 0.f, m3 = 0.f;
#pragma unroll
        for (int ii = 0; ii < 16; ++ii) {
            const float p = sUr[ii][j] * sUr[ii][k] + sUi[ii][j] * sUi[ii][k];
            m0 += (ii & 8) ? -p : p;
            m1 += (ii & 4) ? -p : p;
            m2 += (ii & 2) ? -p : p;
            m3 += (ii & 1) ? -p : p;
        }
        sM[tid * 4 + 0] = m0; sM[tid * 4 + 1] = m1;
        sM[tid * 4 + 2] = m2; sM[tid * 4 + 3] = m3;
    }
    __syncthreads();

    if (tid < 81) {  // project M_w onto (1, cos, sin)^{x4} basis
        const int t0 = tid / 27, t1 = (tid / 9) % 3, t2 = (tid / 3) % 3, t3 = tid % 3;
        const int tt[4] = {t0, t1, t2, t3};
        float a0 = 0.f, a1 = 0.f, a2 = 0.f, a3 = 0.f;
#pragma unroll
        for (int b = 0; b < 16; ++b) {
            int j = 0, k = 0; float sgn = 1.0f;
#pragma unroll
            for (int q = 0; q < 4; ++q) {
                const int o = (b >> q) & 1;
                const int ti = tt[q];
                int jq, kq;
                if (ti == 2) { jq = o; kq = 1 - o; }
                else { jq = o; kq = o; if (ti == 1 && o) sgn = -sgn; }
                j = (j << 1) | jq;
                k = (k << 1) | kq;
            }
            const float* m = &sM[(j * 16 + k) * 4];
            a0 += sgn * m[0]; a1 += sgn * m[1];
            a2 += sgn * m[2]; a3 += sgn * m[3];
        }
        const int u = t0 * 3 + t1, v = t2 * 3 + t3;
        shC[2 * (u * 9 + v)]     = pk2(a0 * 0.0625f, a1 * 0.0625f);
        shC[2 * (u * 9 + v) + 1] = pk2(a2 * 0.0625f, a3 * 0.0625f);
    }
    __syncthreads();

    // ================= evaluation: grid-stride, minimal live set =================
    const ulonglong2* __restrict__ C2 = reinterpret_cast<const ulonglong2*>(shC);
    const ull ONE = pk2(1.0f, 1.0f);

    while (idx < B) {
        // features for qubits 2,3 first (consumes xv.z/.w)
        float c2, s2, c3, s3;
        __sincosf(xv.z, &s2, &c2);
        __sincosf(xv.w, &s3, &c3);
        ull p23[9];
        {
            const ull c2d = pk2(c2, c2), s2d = pk2(s2, s2);
            const ull c3d = pk2(c3, c3), s3d = pk2(s3, s3);
            p23[0] = ONE; p23[1] = c3d; p23[2] = s3d;
            p23[3] = c2d; p23[4] = mul2(c2d, c3d); p23[5] = mul2(c2d, s3d);
            p23[6] = s2d; p23[7] = mul2(s2d, c3d); p23[8] = mul2(s2d, s3d);
        }
        // qubits 0,1 factors (consumes xv.x/.y -> xv dead)
        float c0, s0, c1, s1;
        __sincosf(xv.x, &s0, &c0);
        __sincosf(xv.y, &s1, &c1);
        const float f0a[3] = {1.0f, c0, s0};
        const float f1a[3] = {1.0f, c1, s1};

        // prefetch next chunk into the (now dead) xv registers
        const int nidx = idx + STRIDE;
        if (nidx < B) xv = x[nidx];

        // contraction: z = sum_u p01[u] * (sum_v C[u][v] * p23[v])
        ull zlo = 0ull, zhi = 0ull;
#pragma unroll
        for (int u = 0; u < 9; ++u) {
            ull alo = 0ull, ahi = 0ull;
#pragma unroll
            for (int v = 0; v < 9; ++v) {
                const ulonglong2 c = C2[u * 9 + v];   // LDS.128 warp-uniform
                alo = fma2(c.x, p23[v], alo);
                ahi = fma2(c.y, p23[v], ahi);
            }
            const float puf = f0a[u / 3] * f1a[u % 3];  // 1.0 factors fold away
            const ull pu = pk2(puf, puf);
            zlo = fma2(alo, pu, zlo);
            zhi = fma2(ahi, pu, zhi);
        }

        float z0, z1, z2, z3;
        upk2(zlo, z0, z1); upk2(zhi, z2, z3);
        out[idx] = make_float4(z0, z1, z2, z3);

        idx = nidx;
    }
}

// ---------------------------------------------------------------------------
extern "C" void kernel_launch(void* const* d_in, const int* in_sizes, int n_in,
                              void* d_out, int out_size) {
    int bx = 0, bw = 1;
    if (n_in >= 2 && in_sizes[0] == 60) { bx = 1; bw = 0; }
    const float* x   = (const float*)d_in[bx];
    const float* wts = (const float*)d_in[bw];
    const int B = in_sizes[bx] / 4;

    qlayer_fused_kernel<<<NBLK, TPB>>>((const float4*)x, (float4*)d_out, B, wts);
}

// round 8
// speedup vs baseline: 1.7264x; 1.7264x over previous
#include <cuda_runtime.h>

// QuantumLayer fused single-kernel, UNCAPPED registers (caps proved to force
// spills; uncapped kernels never spilled in R2-R4):
//  z_w(x) = sum_{u,v} C[w][u][v]*p01[u]*p23[v], features (1, cos x, sin x).
// TPB=128 for allocation granularity: ~96 regs -> 5 blocks/SM = 20 warps/SM.
// Every block builds C in parallel (~1.5us wall across the whole chip), then
// grid-strides with packed f32x2 evaluation.

#define TPB    128
#define NBLK   740                 // 5 blocks/SM * 148 SMs target residency
#define STRIDE (NBLK * TPB)

typedef unsigned long long ull;

__device__ __forceinline__ ull pk2(float lo, float hi) {
    ull r; asm("mov.b64 %0,{%1,%2};" : "=l"(r) : "f"(lo), "f"(hi)); return r;
}
__device__ __forceinline__ void upk2(ull a, float& lo, float& hi) {
    asm("mov.b64 {%0,%1},%2;" : "=f"(lo), "=f"(hi) : "l"(a));
}
__device__ __forceinline__ ull fma2(ull a, ull b, ull c) {
    ull d; asm("fma.rn.f32x2 %0,%1,%2,%3;" : "=l"(d) : "l"(a), "l"(b), "l"(c)); return d;
}
__device__ __forceinline__ ull mul2(ull a, ull b) {
    ull d; asm("mul.rn.f32x2 %0,%1,%2;" : "=l"(d) : "l"(a), "l"(b)); return d;
}

__global__ void qlayer_fused_kernel(const float4* __restrict__ x,
                                    float4* __restrict__ out,
                                    int B, const float* __restrict__ weights) {
    __shared__ float sUr[16][16], sUi[16][16];
    __shared__ float sM[256 * 4];                 // [(j*16+k)*4 + w]
    __shared__ __align__(16) ull shC[162];        // [uv][{w01, w23}]

    const int tid = threadIdx.x;

    // ---- first chunk's global load issued before builder (latency hides) ----
    int idx = blockIdx.x * TPB + tid;
    float4 xv = make_float4(0.f, 0.f, 0.f, 0.f);
    if (idx < B) xv = x[idx];

    // ================= builder: weights -> C (per block, 128 thr) =============
    {
        const int i  = tid & 15;                  // row (state index)
        const int jb = tid >> 4;                  // columns jb and jb+8
        float vr0 = (i == jb)     ? 1.0f : 0.0f, vi0 = 0.0f;
        float vr1 = (i == jb + 8) ? 1.0f : 0.0f, vi1 = 0.0f;
#pragma unroll
        for (int l = 0; l < 5; ++l) {
#pragma unroll
            for (int w = 0; w < 4; ++w) {
                const float phi   = __ldg(&weights[(l * 4 + w) * 3 + 0]);
                const float theta = __ldg(&weights[(l * 4 + w) * 3 + 1]);
                const float omega = __ldg(&weights[(l * 4 + w) * 3 + 2]);
                float sp, cp, sm, cm, st, ct;
                __sincosf(0.5f * (phi + omega), &sp, &cp);
                __sincosf(0.5f * (phi - omega), &sm, &cm);
                __sincosf(0.5f * theta, &st, &ct);
                const int m = 8 >> w;
                const float pr0 = __shfl_xor_sync(0xffffffffu, vr0, m);
                const float pi0 = __shfl_xor_sync(0xffffffffu, vi0, m);
                const float pr1 = __shfl_xor_sync(0xffffffffu, vr1, m);
                const float pi1 = __shfl_xor_sync(0xffffffffu, vi1, m);
                const bool bit = (i & m) != 0;
                const float cAr = cp * ct;
                const float cAi = bit ? sp * ct : -sp * ct;
                const float cBr = bit ? cm * st : -cm * st;
                const float cBi = -sm * st;
                float t;
                t   = cAr * vr0 - cAi * vi0 + cBr * pr0 - cBi * pi0;
                vi0 = cAr * vi0 + cAi * vr0 + cBr * pi0 + cBi * pr0;
                vr0 = t;
                t   = cAr * vr1 - cAi * vi1 + cBr * pr1 - cBi * pi1;
                vi1 = cAr * vi1 + cAi * vr1 + cBr * pi1 + cBi * pr1;
                vr1 = t;
            }
            const int r = (l % 3) + 1;
#pragma unroll
            for (int w = 0; w < 4; ++w) {
                const int mc = 8 >> w;
                const int mt = 8 >> ((w + r) & 3);
                const float pr0 = __shfl_xor_sync(0xffffffffu, vr0, mt);
                const float pi0 = __shfl_xor_sync(0xffffffffu, vi0, mt);
                const float pr1 = __shfl_xor_sync(0xffffffffu, vr1, mt);
                const float pi1 = __shfl_xor_sync(0xffffffffu, vi1, mt);
                if (i & mc) { vr0 = pr0; vi0 = pi0; vr1 = pr1; vi1 = pi1; }
            }
        }
        sUr[i][jb]     = vr0;  sUi[i][jb]     = vi0;
        sUr[i][jb + 8] = vr1;  sUi[i][jb + 8] = vi1;
    }
    __syncthreads();

    {   // M_w[j][k] = sum_i sign_w(i) Re(conj U_ij * U_ik), 2 entries/thread
#pragma unroll
        for (int p = tid; p < 256; p += TPB) {
            const int j = p >> 4, k = p & 15;
            float m0 = 0.f, m1 = 0.f, m2 = 0.f, m3 = 0.f;
#pragma unroll
            for (int ii = 0; ii < 16; ++ii) {
                const float pv = sUr[ii][j] * sUr[ii][k] + sUi[ii][j] * sUi[ii][k];
                m0 += (ii & 8) ? -pv : pv;
                m1 += (ii & 4) ? -pv : pv;
                m2 += (ii & 2) ? -pv : pv;
                m3 += (ii & 1) ? -pv : pv;
            }
            sM[p * 4 + 0] = m0; sM[p * 4 + 1] = m1;
            sM[p * 4 + 2] = m2; sM[p * 4 + 3] = m3;
        }
    }
    __syncthreads();

    if (tid < 81) {  // project M_w onto (1, cos, sin)^{x4} basis
        const int t0 = tid / 27, t1 = (tid / 9) % 3, t2 = (tid / 3) % 3, t3 = tid % 3;
        const int tt[4] = {t0, t1, t2, t3};
        float a0 = 0.f, a1 = 0.f, a2 = 0.f, a3 = 0.f;
#pragma unroll
        for (int b = 0; b < 16; ++b) {
            int j = 0, k = 0; float sgn = 1.0f;
#pragma unroll
            for (int q = 0; q < 4; ++q) {
                const int o = (b >> q) & 1;
                const int ti = tt[q];
                int jq, kq;
                if (ti == 2) { jq = o; kq = 1 - o; }
                else { jq = o; kq = o; if (ti == 1 && o) sgn = -sgn; }
                j = (j << 1) | jq;
                k = (k << 1) | kq;
            }
            const float* m = &sM[(j * 16 + k) * 4];
            a0 += sgn * m[0]; a1 += sgn * m[1];
            a2 += sgn * m[2]; a3 += sgn * m[3];
        }
        const int u = t0 * 3 + t1, v = t2 * 3 + t3;
        shC[2 * (u * 9 + v)]     = pk2(a0 * 0.0625f, a1 * 0.0625f);
        shC[2 * (u * 9 + v) + 1] = pk2(a2 * 0.0625f, a3 * 0.0625f);
    }
    __syncthreads();

    // ================= evaluation: grid-stride, uncapped regs =================
    const ulonglong2* __restrict__ C2 = reinterpret_cast<const ulonglong2*>(shC);
    const ull ONE = pk2(1.0f, 1.0f);

    while (idx < B) {
        // features for qubits 2,3 (consumes xv.z/.w)
        float c2, s2, c3, s3;
        __sincosf(xv.z, &s2, &c2);
        __sincosf(xv.w, &s3, &c3);
        ull p23[9];
        {
            const ull c2d = pk2(c2, c2), s2d = pk2(s2, s2);
            const ull c3d = pk2(c3, c3), s3d = pk2(s3, s3);
            p23[0] = ONE; p23[1] = c3d; p23[2] = s3d;
            p23[3] = c2d; p23[4] = mul2(c2d, c3d); p23[5] = mul2(c2d, s3d);
            p23[6] = s2d; p23[7] = mul2(s2d, c3d); p23[8] = mul2(s2d, s3d);
        }
        // qubits 0,1 factors (consumes xv.x/.y -> xv dead)
        float c0, s0, c1, s1;
        __sincosf(xv.x, &s0, &c0);
        __sincosf(xv.y, &s1, &c1);
        const float f0a[3] = {1.0f, c0, s0};
        const float f1a[3] = {1.0f, c1, s1};

        // prefetch next chunk into the (now dead) xv registers
        const int nidx = idx + STRIDE;
        if (nidx < B) xv = x[nidx];

        // contraction: z = sum_u p01[u] * (sum_v C[u][v] * p23[v])
        ull zlo = 0ull, zhi = 0ull;
#pragma unroll
        for (int u = 0; u < 9; ++u) {
            ull alo = 0ull, ahi = 0ull;
#pragma unroll
            for (int v = 0; v < 9; ++v) {
                const ulonglong2 c = C2[u * 9 + v];   // LDS.128 warp-uniform
                alo = fma2(c.x, p23[v], alo);
                ahi = fma2(c.y, p23[v], ahi);
            }
            const float puf = f0a[u / 3] * f1a[u % 3];  // static idx, 1.0 folds
            const ull pu = pk2(puf, puf);
            zlo = fma2(alo, pu, zlo);
            zhi = fma2(ahi, pu, zhi);
        }

        float z0, z1, z2, z3;
        upk2(zlo, z0, z1); upk2(zhi, z2, z3);
        out[idx] = make_float4(z0, z1, z2, z3);

        idx = nidx;
    }
}

// ---------------------------------------------------------------------------
extern "C" void kernel_launch(void* const* d_in, const int* in_sizes, int n_in,
                              void* d_out, int out_size) {
    int bx = 0, bw = 1;
    if (n_in >= 2 && in_sizes[0] == 60) { bx = 1; bw = 0; }
    const float* x   = (const float*)d_in[bx];
    const float* wts = (const float*)d_in[bw];
    const int B = in_sizes[bx] / 4;

    qlayer_fused_kernel<<<NBLK, TPB>>>((const float4*)x, (float4*)d_out, B, wts);
}